// round 11
// baseline (speedup 1.0000x reference)
#include <cuda_runtime.h>
#include <math_constants.h>

// SpatialAttention: out = x * hardsigmoid(conv3x3([mean_c(x); max_c(x)]))
// x: [16, 256, 128, 128] fp32, conv_w: [1, 2, 3, 3] fp32.
//
// Two-stream pipeline (R9/R10) + reshaped reduce:
//  - reduce: 2 channel-halves x 128 col-strips per chunk; block = 256 thr
//    (32 cols x 8 groups x 16 ch). Every warp load = one 512B contiguous
//    segment (R10's 256B segments capped reduce at 2.46 TB/s; R2's 512B
//    shape ran ~4 TB/s). Partial sum/max per half -> g_pavg/g_pmax.
//  - conv folds the two halves on the fly (no combine kernel).
//  - mul unchanged: x from L2 (__ldcs), out streamed (__stcs).

#define BATCH 16
#define CH    256
#define HH    128
#define WW    128
#define HWSZ  (HH * WW)          // 16384
#define HW4   (HWSZ / 4)         // 4096 float4 cols per (b,c) plane
#define NCHNK 16                 // 1 batch per chunk (16 MiB x-slice)

#define R_BLK 256                // 2 halves x 128 strips
#define C_BLK 64
#define M_BLK 4096

__device__ float g_pavg[2][BATCH * HWSZ];   // per-half partial sums
__device__ float g_pmax[2][BATCH * HWSZ];   // per-half partial maxes
__device__ float g_att[BATCH * HWSZ];

// ---------------------------------------------------------------------------
// reduce: block (half, strip). 256 thr = 32 cols x 8 groups; each group
// covers 16 channels of its half. Warp load = 512B contiguous.
// ---------------------------------------------------------------------------
__global__ void __launch_bounds__(256) reduce_kernel(const float* __restrict__ x, int b) {
    __shared__ float4 ssum[256];
    __shared__ float4 smax[256];

    int t       = threadIdx.x;
    int half    = blockIdx.x >> 7;        // 0,1
    int strip   = blockIdx.x & 127;
    int colBase = strip * 32;
    int col_l   = t & 31;
    int cg      = t >> 5;                 // 0..7

    const float4* xp = reinterpret_cast<const float4*>(x)
                     + (size_t)b * CH * HW4
                     + (size_t)(half * 128 + cg * 16) * HW4
                     + colBase + col_l;

    float4 s = make_float4(0.f, 0.f, 0.f, 0.f);
    float4 m = make_float4(-CUDART_INF_F, -CUDART_INF_F, -CUDART_INF_F, -CUDART_INF_F);

    #pragma unroll
    for (int c = 0; c < 16; c++) {        // 16 independent 512B warp loads
        float4 v = xp[c * HW4];
        s.x += v.x; s.y += v.y; s.z += v.z; s.w += v.w;
        m.x = fmaxf(m.x, v.x); m.y = fmaxf(m.y, v.y);
        m.z = fmaxf(m.z, v.z); m.w = fmaxf(m.w, v.w);
    }
    ssum[t] = s; smax[t] = m;
    __syncthreads();

    #pragma unroll
    for (int off = 128; off >= 32; off >>= 1) {
        if (t < off) {
            float4 s2 = ssum[t + off], m2 = smax[t + off];
            float4 sa = ssum[t],       ma = smax[t];
            sa.x += s2.x; sa.y += s2.y; sa.z += s2.z; sa.w += s2.w;
            ma.x = fmaxf(ma.x, m2.x); ma.y = fmaxf(ma.y, m2.y);
            ma.z = fmaxf(ma.z, m2.z); ma.w = fmaxf(ma.w, m2.w);
            ssum[t] = sa; smax[t] = ma;
        }
        __syncthreads();
    }

    if (t < 32) {
        reinterpret_cast<float4*>(g_pavg[half])[b * HW4 + colBase + t] = ssum[t];
        reinterpret_cast<float4*>(g_pmax[half])[b * HW4 + colBase + t] = smax[t];
    }
}

// ---------------------------------------------------------------------------
// conv: folds the two channel-halves on the fly, 3x3 conv, hardsigmoid.
// ---------------------------------------------------------------------------
__global__ void __launch_bounds__(256) conv_kernel(const float* __restrict__ wt, int b) {
    int idx = blockIdx.x * 256 + threadIdx.x;   // 0 .. HWSZ-1
    int h   = idx >> 7;
    int w   = idx & (WW - 1);

    const float* __restrict__ A0 = g_pavg[0] + b * HWSZ;
    const float* __restrict__ A1 = g_pavg[1] + b * HWSZ;
    const float* __restrict__ M0 = g_pmax[0] + b * HWSZ;
    const float* __restrict__ M1 = g_pmax[1] + b * HWSZ;

    const float inv = 1.0f / (float)CH;

    float acc = 0.f;
    #pragma unroll
    for (int kh = 0; kh < 3; kh++) {
        int hh = h + kh - 1;
        if (hh < 0 || hh >= HH) continue;
        #pragma unroll
        for (int kw = 0; kw < 3; kw++) {
            int ww = w + kw - 1;
            if (ww < 0 || ww >= WW) continue;
            int o = hh * WW + ww;
            float avg = (A0[o] + A1[o]) * inv;
            float mx  = fmaxf(M0[o], M1[o]);
            acc += __ldg(&wt[kh * 3 + kw])     * avg
                 + __ldg(&wt[9 + kh * 3 + kw]) * mx;
        }
    }
    float y = fminf(fmaxf(acc + 3.0f, 0.0f), 6.0f) * (1.0f / 6.0f);
    g_att[b * HWSZ + idx] = y;
}

// ---------------------------------------------------------------------------
__global__ void __launch_bounds__(256) mul_kernel(const float* __restrict__ x,
                                                  float* __restrict__ out, int b) {
    int idx = blockIdx.x * 256 + threadIdx.x;   // 0 .. CH*HW4-1
    int col = idx & (HW4 - 1);

    size_t gidx = (size_t)b * CH * HW4 + idx;

    float4 v = __ldcs(reinterpret_cast<const float4*>(x) + gidx);
    float4 a = __ldg(reinterpret_cast<const float4*>(g_att) + (size_t)b * HW4 + col);

    v.x *= a.x; v.y *= a.y; v.z *= a.z; v.w *= a.w;
    __stcs(reinterpret_cast<float4*>(out) + gidx, v);
}

// ---------------------------------------------------------------------------
extern "C" void kernel_launch(void* const* d_in, const int* in_sizes, int n_in,
                              void* d_out, int out_size) {
    const float* x  = (const float*)d_in[0];
    const float* wt = (const float*)d_in[1];
    float* out      = (float*)d_out;

    static cudaStream_t sB = []() {
        cudaStream_t s;
        cudaStreamCreateWithFlags(&s, cudaStreamNonBlocking);
        return s;
    }();
    static cudaEvent_t evFork = []() {
        cudaEvent_t e;
        cudaEventCreateWithFlags(&e, cudaEventDisableTiming);
        return e;
    }();
    static cudaEvent_t evJoin = []() {
        cudaEvent_t e;
        cudaEventCreateWithFlags(&e, cudaEventDisableTiming);
        return e;
    }();

    // Fork second stream into the captured graph.
    cudaEventRecord(evFork, 0);
    cudaStreamWaitEvent(sB, evFork, 0);

    // Even chunks on capture stream, odd chunks on sB.
    for (int b = 0; b < NCHNK; b++) {
        cudaStream_t s = (b & 1) ? sB : (cudaStream_t)0;
        reduce_kernel<<<R_BLK, 256, 0, s>>>(x, b);
        conv_kernel<<<C_BLK, 256, 0, s>>>(wt, b);
        mul_kernel<<<M_BLK, 256, 0, s>>>(x, out, b);
    }

    // Join.
    cudaEventRecord(evJoin, sB);
    cudaStreamWaitEvent(0, evJoin, 0);
}

// round 12
// speedup vs baseline: 1.0516x; 1.0516x over previous
#include <cuda_runtime.h>
#include <math_constants.h>

// SpatialAttention: out = x * hardsigmoid(conv3x3([mean_c(x); max_c(x)]))
// x: [16, 256, 128, 128] fp32, conv_w: [1, 2, 3, 3] fp32.
//
// Two-stream pipeline (R10 structure, best=134.2us) + MLP-forced reduce:
// the reduce loop loads ALL 8 channel float4s into a live register array
// BEFORE accumulating. Every prior variant compiled to regs=32 => ~1 load
// in flight per thread => reduce pinned at 2.2-2.5 TB/s regardless of
// occupancy/shape. Batched loads force 8 outstanding LDG.128 per thread.

#define BATCH 16
#define CH    256
#define HH    128
#define WW    128
#define HWSZ  (HH * WW)          // 16384
#define HW4   (HWSZ / 4)         // 4096 float4 cols per (b,c) plane
#define NCHNK 16                 // 1 batch per chunk (16 MiB x-slice)

#define COLS_PER_BLK 16
#define RTHREADS 512
#define NGRP  (RTHREADS / COLS_PER_BLK)   // 32 channel groups
#define CPS   (CH / NGRP)                 // 8 channels per group

#define R_BLK 256                // reduce blocks per chunk (HW4/16)
#define C_BLK 64
#define M_BLK 4096

__device__ float g_avg[BATCH * HWSZ];
__device__ float g_max[BATCH * HWSZ];
__device__ float g_att[BATCH * HWSZ];

// ---------------------------------------------------------------------------
__global__ void __launch_bounds__(RTHREADS) reduce_kernel(const float* __restrict__ x, int b) {
    __shared__ float4 ssum[RTHREADS];
    __shared__ float4 smax[RTHREADS];

    int t       = threadIdx.x;
    int colBase = blockIdx.x * COLS_PER_BLK;
    int col_l   = t & (COLS_PER_BLK - 1);
    int cg      = t >> 4;                 // 0..31 channel group

    const float4* xp = reinterpret_cast<const float4*>(x)
                     + (size_t)b * CH * HW4 + (size_t)cg * CPS * HW4
                     + colBase + col_l;

    // Batch ALL loads first -> 8 independent LDG.128 in flight per thread.
    float4 v[CPS];
    #pragma unroll
    for (int c = 0; c < CPS; c++) v[c] = xp[c * HW4];

    float4 s = v[0];
    float4 m = v[0];
    #pragma unroll
    for (int c = 1; c < CPS; c++) {
        s.x += v[c].x; s.y += v[c].y; s.z += v[c].z; s.w += v[c].w;
        m.x = fmaxf(m.x, v[c].x); m.y = fmaxf(m.y, v[c].y);
        m.z = fmaxf(m.z, v[c].z); m.w = fmaxf(m.w, v[c].w);
    }
    ssum[t] = s; smax[t] = m;
    __syncthreads();

    #pragma unroll
    for (int off = RTHREADS / 2; off >= COLS_PER_BLK; off >>= 1) {
        if (t < off) {
            float4 s2 = ssum[t + off], m2 = smax[t + off];
            float4 sa = ssum[t],       ma = smax[t];
            sa.x += s2.x; sa.y += s2.y; sa.z += s2.z; sa.w += s2.w;
            ma.x = fmaxf(ma.x, m2.x); ma.y = fmaxf(ma.y, m2.y);
            ma.z = fmaxf(ma.z, m2.z); ma.w = fmaxf(ma.w, m2.w);
            ssum[t] = sa; smax[t] = ma;
        }
        __syncthreads();
    }

    if (t < COLS_PER_BLK) {
        const float inv = 1.0f / (float)CH;
        float4 sa = ssum[t], ma = smax[t];
        float4 a = make_float4(sa.x * inv, sa.y * inv, sa.z * inv, sa.w * inv);
        reinterpret_cast<float4*>(g_avg)[b * HW4 + colBase + t] = a;
        reinterpret_cast<float4*>(g_max)[b * HW4 + colBase + t] = ma;
    }
}

// ---------------------------------------------------------------------------
__global__ void __launch_bounds__(256) conv_kernel(const float* __restrict__ wt, int b) {
    int idx = blockIdx.x * 256 + threadIdx.x;   // 0 .. HWSZ-1
    int h   = idx >> 7;
    int w   = idx & (WW - 1);

    const float* __restrict__ A = g_avg + b * HWSZ;
    const float* __restrict__ M = g_max + b * HWSZ;

    float acc = 0.f;
    #pragma unroll
    for (int kh = 0; kh < 3; kh++) {
        int hh = h + kh - 1;
        if (hh < 0 || hh >= HH) continue;
        #pragma unroll
        for (int kw = 0; kw < 3; kw++) {
            int ww = w + kw - 1;
            if (ww < 0 || ww >= WW) continue;
            int o = hh * WW + ww;
            acc += __ldg(&wt[kh * 3 + kw])     * A[o]
                 + __ldg(&wt[9 + kh * 3 + kw]) * M[o];
        }
    }
    float y = fminf(fmaxf(acc + 3.0f, 0.0f), 6.0f) * (1.0f / 6.0f);
    g_att[b * HWSZ + idx] = y;
}

// ---------------------------------------------------------------------------
__global__ void __launch_bounds__(256) mul_kernel(const float* __restrict__ x,
                                                  float* __restrict__ out, int b) {
    int idx = blockIdx.x * 256 + threadIdx.x;   // 0 .. CH*HW4-1
    int col = idx & (HW4 - 1);

    size_t gidx = (size_t)b * CH * HW4 + idx;

    float4 v = __ldcs(reinterpret_cast<const float4*>(x) + gidx);
    float4 a = __ldg(reinterpret_cast<const float4*>(g_att) + (size_t)b * HW4 + col);

    v.x *= a.x; v.y *= a.y; v.z *= a.z; v.w *= a.w;
    __stcs(reinterpret_cast<float4*>(out) + gidx, v);
}

// ---------------------------------------------------------------------------
extern "C" void kernel_launch(void* const* d_in, const int* in_sizes, int n_in,
                              void* d_out, int out_size) {
    const float* x  = (const float*)d_in[0];
    const float* wt = (const float*)d_in[1];
    float* out      = (float*)d_out;

    static cudaStream_t sB = []() {
        cudaStream_t s;
        cudaStreamCreateWithFlags(&s, cudaStreamNonBlocking);
        return s;
    }();
    static cudaEvent_t evFork = []() {
        cudaEvent_t e;
        cudaEventCreateWithFlags(&e, cudaEventDisableTiming);
        return e;
    }();
    static cudaEvent_t evJoin = []() {
        cudaEvent_t e;
        cudaEventCreateWithFlags(&e, cudaEventDisableTiming);
        return e;
    }();

    // Fork second stream into the captured graph.
    cudaEventRecord(evFork, 0);
    cudaStreamWaitEvent(sB, evFork, 0);

    // Even chunks on capture stream, odd chunks on sB.
    for (int b = 0; b < NCHNK; b++) {
        cudaStream_t s = (b & 1) ? sB : (cudaStream_t)0;
        reduce_kernel<<<R_BLK, RTHREADS, 0, s>>>(x, b);
        conv_kernel<<<C_BLK, 256, 0, s>>>(wt, b);
        mul_kernel<<<M_BLK, 256, 0, s>>>(x, out, b);
    }

    // Join.
    cudaEventRecord(evJoin, sB);
    cudaStreamWaitEvent(0, evJoin, 0);
}